// round 7
// baseline (speedup 1.0000x reference)
#include <cuda_runtime.h>

#define BB 64
#define SZ 2048
#define LL 16
#define AA 64
#define HH 256
#define RR 65536
#define XW (SZ + LL)
#define BPB 4   // buckets per step-block -> 512 blocks

// ---------------- scratch (static device globals; no allocs) ----------------
__device__ __align__(16) float    g_P1[SZ * HH];
__device__ __align__(16) float    g_P2[SZ * HH];
__device__ __align__(16) unsigned g_relT[RR * AA];        // relation rows as tf32 bits, CSR order
__device__ __align__(16) unsigned g_metaT32[LL * BB * AA]; // tf32 bits, [(t*64+b)][k]
__device__ __align__(16) float    g_stateAll[LL + 1][SZ * BB]; // [t][o][b]
__device__ int g_perm[RR];
__device__ int g_subjS[RR];
__device__ int g_objS[RR];
__device__ int g_counts[SZ];
__device__ int g_rowptr[SZ + 1];
__device__ int g_offs[SZ];

// ---------------- tf32 mma helpers ----------------
__device__ __forceinline__ unsigned f2t(float f) {
    unsigned u;
    asm("cvt.rna.tf32.f32 %0, %1;" : "=r"(u) : "f"(f));
    return u;
}
__device__ __forceinline__ void mma8(float4& d, unsigned a0, unsigned a1, unsigned a2,
                                     unsigned a3, unsigned b0, unsigned b1) {
    asm volatile(
        "mma.sync.aligned.m16n8k8.row.col.f32.tf32.tf32.f32 "
        "{%0,%1,%2,%3},{%4,%5,%6,%7},{%8,%9},{%0,%1,%2,%3};"
        : "+f"(d.x), "+f"(d.y), "+f"(d.z), "+f"(d.w)
        : "r"(a0), "r"(a1), "r"(a2), "r"(a3), "r"(b0), "r"(b1));
}

__device__ __forceinline__ float sigf(float v) {
    return __fdividef(1.f, 1.f + __expf(-v));
}

// ---------------- CSR build (deterministic) ----------------
__global__ void k_zero() {
    int i = blockIdx.x * blockDim.x + threadIdx.x;
    if (i < SZ) g_counts[i] = 0;
}

__global__ void k_hist(const int* __restrict__ robj) {
    int e = blockIdx.x * blockDim.x + threadIdx.x;
    if (e < RR) atomicAdd(&g_counts[robj[e]], 1);
}

__global__ void k_scan() {  // 1 block, 1024 threads: scan of 2048
    __shared__ int sA[SZ], sB[SZ];
    int tid = threadIdx.x;
    for (int i = tid; i < SZ; i += 1024) sA[i] = g_counts[i];
    __syncthreads();
    int* src = sA; int* dst = sB;
    for (int off = 1; off < SZ; off <<= 1) {
        for (int i = tid; i < SZ; i += 1024)
            dst[i] = src[i] + (i >= off ? src[i - off] : 0);
        __syncthreads();
        int* t = src; src = dst; dst = t;
    }
    for (int i = tid; i < SZ; i += 1024) {
        g_rowptr[i + 1] = src[i];
        g_offs[i] = (i == 0) ? 0 : src[i - 1];
    }
    if (tid == 0) g_rowptr[0] = 0;
}

__global__ void k_scatter(const int* __restrict__ robj) {
    int e = blockIdx.x * blockDim.x + threadIdx.x;
    if (e < RR) {
        int pos = atomicAdd(&g_offs[robj[e]], 1);
        g_perm[pos] = e;
    }
}

// sort each bucket's edge ids ascending (determinism), emit subj/obj in sorted order
__global__ void k_bsort(const int* __restrict__ rsub) {
    __shared__ int buf[8][208];
    int wid = threadIdx.x >> 5, lane = threadIdx.x & 31;
    int o = blockIdx.x * 8 + wid;
    int s = g_rowptr[o], e = g_rowptr[o + 1], n = e - s;
    if (n > 0 && n <= 208) {
        for (int i = lane; i < n; i += 32) buf[wid][i] = g_perm[s + i];
        __syncwarp();
        for (int r = 0; r < n; r++) {           // odd-even transposition
            int par = r & 1;
            for (int i = par + 2 * lane; i + 1 < n; i += 64) {
                int a = buf[wid][i], b = buf[wid][i + 1];
                if (a > b) { buf[wid][i] = b; buf[wid][i + 1] = a; }
            }
            __syncwarp();
        }
        for (int i = lane; i < n; i += 32) {
            int p = buf[wid][i];
            g_perm[s + i] = p;
            g_subjS[s + i] = rsub[p];
            g_objS[s + i] = o;
        }
    } else {
        for (int i = lane; i < n; i += 32) {
            int p = g_perm[s + i];
            g_subjS[s + i] = rsub[p];
            g_objS[s + i] = o;
        }
    }
}

// ---------------- P1/P2 = state_emb @ W1 halves ----------------
__global__ void k_p12(const float* __restrict__ emb, const float* __restrict__ w1) {
    __shared__ float es[8][64];
    int tid = threadIdx.x;
    int r0 = blockIdx.x * 8;
    for (int i = tid; i < 512; i += 256) es[i >> 6][i & 63] = emb[r0 * 64 + i];
    __syncthreads();
    float a1[8], a2[8];
#pragma unroll
    for (int r = 0; r < 8; r++) { a1[r] = 0.f; a2[r] = 0.f; }
    for (int k = 0; k < 64; k++) {
        float wa = w1[k * HH + tid];
        float wb = w1[(64 + k) * HH + tid];
#pragma unroll
        for (int r = 0; r < 8; r++) {
            a1[r] += es[r][k] * wa;
            a2[r] += es[r][k] * wb;
        }
    }
#pragma unroll
    for (int r = 0; r < 8; r++) {
        g_P1[(r0 + r) * HH + tid] = a1[r];
        g_P2[(r0 + r) * HH + tid] = a2[r];
    }
}

// ---------------- relation rows via tf32 mma; output tf32 bits ----------------
// block: 64 edges, N=64, K=256 in 4 chunks of 64. 256 threads = 8 warps (4m x 2n).
__global__ void k_rel2(const float* __restrict__ b1v, const float* __restrict__ w2,
                       const float* __restrict__ b2v) {
    __shared__ float hs[64][68];
    __shared__ float ws[64][68];
    __shared__ int ssub[64], sobj[64];
    int tid = threadIdx.x;
    int e0 = blockIdx.x * 64;
    if (tid < 64) { ssub[tid] = g_subjS[e0 + tid]; sobj[tid] = g_objS[e0 + tid]; }
    __syncthreads();
    int warp = tid >> 5, lane = tid & 31;
    int wm = warp & 3, wn = warp >> 2;
    int g = lane >> 2, tg = lane & 3;
    int r0 = wm * 16, n0 = wn * 32;
    float4 acc[4] = {};
    for (int kc = 0; kc < 4; kc++) {
        for (int i = tid; i < 64 * 16; i += 256) {
            int r = i >> 4, c = (i & 15) * 4;
            float4 p1 = *(const float4*)&g_P1[ssub[r] * HH + kc * 64 + c];
            float4 p2 = *(const float4*)&g_P2[sobj[r] * HH + kc * 64 + c];
            float4 bb = *(const float4*)&b1v[kc * 64 + c];
            float4 h;
            h.x = fmaxf(p1.x + p2.x + bb.x, 0.f);
            h.y = fmaxf(p1.y + p2.y + bb.y, 0.f);
            h.z = fmaxf(p1.z + p2.z + bb.z, 0.f);
            h.w = fmaxf(p1.w + p2.w + bb.w, 0.f);
            *(float4*)&hs[r][c] = h;
            *(float4*)&ws[r][c] = *(const float4*)&w2[(kc * 64 + r) * 64 + c];
        }
        __syncthreads();
#pragma unroll
        for (int ks = 0; ks < 8; ks++) {
            int kk = ks * 8;
            unsigned a0 = f2t(hs[r0 + g][kk + tg]);
            unsigned a1 = f2t(hs[r0 + g + 8][kk + tg]);
            unsigned a2 = f2t(hs[r0 + g][kk + tg + 4]);
            unsigned a3 = f2t(hs[r0 + g + 8][kk + tg + 4]);
#pragma unroll
            for (int nf = 0; nf < 4; nf++) {
                int n = n0 + nf * 8 + g;
                unsigned b0 = f2t(ws[kk + tg][n]);
                unsigned b1 = f2t(ws[kk + tg + 4][n]);
                mma8(acc[nf], a0, a1, a2, a3, b0, b1);
            }
        }
        __syncthreads();
    }
#pragma unroll
    for (int nf = 0; nf < 4; nf++) {
        int col = n0 + nf * 8 + 2 * tg;
        float bx = b2v[col], by = b2v[col + 1];
        int row = e0 + r0 + g;
        uint2 v0 = {f2t(acc[nf].x + bx), f2t(acc[nf].y + by)};
        uint2 v1 = {f2t(acc[nf].z + bx), f2t(acc[nf].w + by)};
        *(uint2*)&g_relT[row * 64 + col] = v0;
        *(uint2*)&g_relT[(row + 8) * 64 + col] = v1;
    }
}

// ---------------- meta recurrence v2: latency-optimized --------------------------
// 16 blocks x 1024 threads; 4 batches/block, 256 threads per batch-group.
// Every dot is k-split across threads + shuffle-reduced; layer1 uses 4 accumulators.
__global__ void __launch_bounds__(1024) k_meta2(
        const int* __restrict__ x, const float* __restrict__ aemb,
        const float* __restrict__ pemb, const float* __restrict__ qw,
        const float* __restrict__ qb, const float* __restrict__ mw1,
        const float* __restrict__ mb1, const float* __restrict__ mw2,
        const float* __restrict__ mb2, const float* __restrict__ minit) {
    __shared__ float sent[4][16][132];
    __shared__ float meta[4][64];
    __shared__ float query[4][128];
    __shared__ float attn[4][16];
    __shared__ float z[4][192];
    __shared__ float hid[4][256];
    int tid = threadIdx.x;
    int g = tid >> 8, t = tid & 255;
    int b = blockIdx.x * 4 + g;

    for (int i = t; i < 16 * 128; i += 256) {
        int l = i >> 7, d = i & 127;
        int a = x[b * XW + SZ + l];
        sent[g][l][d] = (d < 64) ? aemb[a * 64 + d] : pemb[l * 64 + (d - 64)];
    }
    if (t < 64) meta[g][t] = minit[t];
    __syncthreads();

    for (int st = 0; st < 16; st++) {
        // (a) query[j] = meta . qw[:,j] + qb[j]; 2 threads per output
        {
            int j = t >> 1, s = t & 1;
            float q = 0.f;
#pragma unroll
            for (int k = s * 32; k < s * 32 + 32; k++) q += meta[g][k] * qw[k * 128 + j];
            q += __shfl_xor_sync(0xffffffffu, q, 1);
            if (s == 0) query[g][j] = q + qb[j];
        }
        __syncthreads();
        // (b) scores: 16 outputs, 16 threads each
        {
            int l = t >> 4, s = t & 15;
            float sc = 0.f;
#pragma unroll
            for (int i = 0; i < 8; i++) {
                int d = s + 16 * i;
                sc += query[g][d] * sent[g][l][d];
            }
            sc += __shfl_xor_sync(0xffffffffu, sc, 1);
            sc += __shfl_xor_sync(0xffffffffu, sc, 2);
            sc += __shfl_xor_sync(0xffffffffu, sc, 4);
            sc += __shfl_xor_sync(0xffffffffu, sc, 8);
            if (s == 0) attn[g][l] = sc;
        }
        __syncthreads();
        // (c) softmax over 16 (lanes 0-15 of each group's warp 0)
        if (t < 16) {
            float v = attn[g][t];
            float m = v;
#pragma unroll
            for (int o = 8; o; o >>= 1) m = fmaxf(m, __shfl_xor_sync(0xffffu, m, o));
            float e = __expf(v - m);
            float ssum = e;
#pragma unroll
            for (int o = 8; o; o >>= 1) ssum += __shfl_xor_sync(0xffffu, ssum, o);
            attn[g][t] = e / ssum;
        }
        __syncthreads();
        // (d) attended -> z[64+j]; copy meta -> z[0:64]
        {
            int j = t >> 1, s = t & 1;
            float at = 0.f;
#pragma unroll
            for (int l = s * 8; l < s * 8 + 8; l++) at += attn[g][l] * sent[g][l][j];
            at += __shfl_xor_sync(0xffffffffu, at, 1);
            if (s == 0) {
                z[g][64 + j] = at;
                if (j < 64) z[g][j] = meta[g][j];
            }
        }
        __syncthreads();
        // (e) layer1: 256 outputs, 1 thread each, 4 accumulators (48-dep chain)
        {
            float a0 = 0.f, a1 = 0.f, a2 = 0.f, a3 = 0.f;
#pragma unroll
            for (int k = 0; k < 192; k += 4) {
                a0 += z[g][k]     * mw1[k * HH + t];
                a1 += z[g][k + 1] * mw1[(k + 1) * HH + t];
                a2 += z[g][k + 2] * mw1[(k + 2) * HH + t];
                a3 += z[g][k + 3] * mw1[(k + 3) * HH + t];
            }
            hid[g][t] = fmaxf((a0 + a1) + (a2 + a3) + mb1[t], 0.f);
        }
        __syncthreads();
        // (f) layer2: 64 outputs, 4 threads each (k interleaved), 2 accumulators
        {
            int j = t >> 2, s = t & 3;
            float a0 = 0.f, a1 = 0.f;
#pragma unroll
            for (int i = 0; i < 64; i += 2) {
                a0 += hid[g][4 * i + s]     * mw2[(4 * i + s) * 64 + j];
                a1 += hid[g][4 * (i + 1) + s] * mw2[(4 * (i + 1) + s) * 64 + j];
            }
            float m = a0 + a1;
            m += __shfl_xor_sync(0xffffffffu, m, 1);
            m += __shfl_xor_sync(0xffffffffu, m, 2);
            if (s == 0) meta[g][j] = m + mb2[j];
        }
        __syncthreads();
        if (t < 64) g_metaT32[(st * 64 + b) * 64 + t] = f2t(meta[g][t]);
    }
}

// ---------------- init transposed state ----------------
__global__ void k_init(const int* __restrict__ x) {
    int i = blockIdx.x * blockDim.x + threadIdx.x;  // 131072
    int b = i >> 11, o = i & 2047;
    g_stateAll[0][o * 64 + b] = (float)x[b * XW + o];
}

// ---------------- fused step: MMA dots + sigmoid + gather + segmented reduce ------
// block = 4 buckets (512 blocks), 256 threads = 8 warps (4m x 2n) over 64x64 tiles.
__global__ void __launch_bounds__(256) k_stepF(int t) {
    __shared__ __align__(16) unsigned tileBuf[64 * 68];  // rel tf32 bits, reused as prod floats
    __shared__ __align__(16) unsigned metaS[64 * 68];
    __shared__ float acc[(BPB + 1) * 64];
    __shared__ int ssubj[64];
    __shared__ unsigned char rowb[64];
    const float* __restrict__ stIn = g_stateAll[t];
    float* __restrict__ stOut = g_stateAll[t + 1];
    int tid = threadIdx.x;
    int bkt0 = blockIdx.x * BPB;
    int eStart = g_rowptr[bkt0];
    int eEnd = g_rowptr[bkt0 + BPB];

    const unsigned* mt = &g_metaT32[t * 64 * 64];
    for (int i = tid; i < 64 * 16; i += 256) {
        int r = i >> 4, c = (i & 15) * 4;
        *(uint4*)&metaS[r * 68 + c] = *(const uint4*)&mt[r * 64 + c];
    }
    for (int i = tid; i < (BPB + 1) * 64; i += 256) acc[i] = 0.f;
    __syncthreads();

    int warp = tid >> 5, lane = tid & 31;
    int wm = warp & 3, wn = warp >> 2;
    int g = lane >> 2, tg = lane & 3;
    int r0 = wm * 16, n0 = wn * 32;
    int q = tid >> 6, col = tid & 63;

    for (int base = eStart; base < eEnd; base += 64) {
        int m = min(64, eEnd - base);
        // fill rel tile (tf32 bits) + subj + local bucket ids
        for (int i = tid; i < 64 * 16; i += 256) {
            int r = i >> 4, c = (i & 15) * 4;
            uint4 v = (r < m) ? *(const uint4*)&g_relT[(base + r) * 64 + c]
                              : make_uint4(0u, 0u, 0u, 0u);
            *(uint4*)&tileBuf[r * 68 + c] = v;
        }
        if (tid < 64) {
            if (tid < m) {
                ssubj[tid] = g_subjS[base + tid];
                rowb[tid] = (unsigned char)(g_objS[base + tid] - bkt0);
            } else { ssubj[tid] = 0; rowb[tid] = BPB; }
        }
        __syncthreads();

        float4 accf[4] = {};
#pragma unroll
        for (int ks = 0; ks < 8; ks++) {
            int kk = ks * 8;
            unsigned a0 = tileBuf[(r0 + g) * 68 + kk + tg];
            unsigned a1 = tileBuf[(r0 + g + 8) * 68 + kk + tg];
            unsigned a2 = tileBuf[(r0 + g) * 68 + kk + tg + 4];
            unsigned a3 = tileBuf[(r0 + g + 8) * 68 + kk + tg + 4];
#pragma unroll
            for (int nf = 0; nf < 4; nf++) {
                int n = n0 + nf * 8 + g;
                unsigned b0 = metaS[n * 68 + kk + tg];
                unsigned b1 = metaS[n * 68 + kk + tg + 4];
                mma8(accf[nf], a0, a1, a2, a3, b0, b1);
            }
        }
        __syncthreads();  // everyone done reading tileBuf as rel

        // epilogue: prod[e][b] = state[subj[e]][b] * sigmoid(D[e][b]) into tileBuf
        float* prod = (float*)tileBuf;
        int rA = r0 + g, rB = rA + 8;
        int sjA = ssubj[rA], sjB = ssubj[rB];
#pragma unroll
        for (int nf = 0; nf < 4; nf++) {
            int c = n0 + nf * 8 + 2 * tg;
            float2 svA = *(const float2*)&stIn[sjA * 64 + c];
            float2 svB = *(const float2*)&stIn[sjB * 64 + c];
            float2 pA = {svA.x * sigf(accf[nf].x), svA.y * sigf(accf[nf].y)};
            float2 pB = {svB.x * sigf(accf[nf].z), svB.y * sigf(accf[nf].w)};
            *(float2*)&prod[rA * 68 + c] = pA;
            *(float2*)&prod[rB * 68 + c] = pB;
        }
        __syncthreads();

        // segmented reduction: thread (q, col) sums rows [16q,16q+16) by bucket
        {
            float s = 0.f;
            int cur = rowb[q * 16];
#pragma unroll
            for (int r = q * 16; r < q * 16 + 16; r++) {
                int lb = rowb[r];
                if (lb != cur) { atomicAdd(&acc[cur * 64 + col], s); s = 0.f; cur = lb; }
                s += prod[r * 68 + col];
            }
            atomicAdd(&acc[cur * 64 + col], s);
        }
        __syncthreads();
    }

    for (int i = tid; i < BPB * 64; i += 256) {
        int lb = i >> 6, c = i & 63;
        stOut[(bkt0 + lb) * 64 + c] = acc[lb * 64 + c];
    }
}

// ---------------- final transpose: out[b][t][o] = stateAll[t+1][o][b] -------------
__global__ void k_out(float* __restrict__ out) {
    __shared__ float tile[64][65];
    int t = blockIdx.x, o0 = blockIdx.y * 64;
    const float* st = g_stateAll[t + 1];
    for (int i = threadIdx.x; i < 64 * 64; i += 256) {
        int r = i >> 6, b = i & 63;
        tile[b][r] = st[(o0 + r) * 64 + b];
    }
    __syncthreads();
    for (int i = threadIdx.x; i < 64 * 64; i += 256) {
        int b = i >> 6, c = i & 63;
        out[(size_t)b * (LL * SZ) + t * SZ + o0 + c] = tile[b][c];
    }
}

extern "C" void kernel_launch(void* const* d_in, const int* in_sizes, int n_in,
                              void* d_out, int out_size) {
    const int*   x     = (const int*)d_in[0];
    const int*   rsub  = (const int*)d_in[1];
    const int*   robj  = (const int*)d_in[2];
    const float* aemb  = (const float*)d_in[3];
    const float* pemb  = (const float*)d_in[4];
    const float* semb  = (const float*)d_in[5];
    const float* w1    = (const float*)d_in[6];
    const float* b1    = (const float*)d_in[7];
    const float* w2    = (const float*)d_in[8];
    const float* b2    = (const float*)d_in[9];
    const float* qw    = (const float*)d_in[10];
    const float* qb    = (const float*)d_in[11];
    const float* mw1   = (const float*)d_in[12];
    const float* mb1   = (const float*)d_in[13];
    const float* mw2   = (const float*)d_in[14];
    const float* mb2   = (const float*)d_in[15];
    const float* minit = (const float*)d_in[16];
    float* out = (float*)d_out;

    // k_meta2 at the 4th launch slot (ncu profiles that slot).
    k_zero<<<8, 256>>>();
    k_hist<<<256, 256>>>(robj);
    k_scan<<<1, 1024>>>();
    k_meta2<<<16, 1024>>>(x, aemb, pemb, qw, qb, mw1, mb1, mw2, mb2, minit);
    k_scatter<<<256, 256>>>(robj);
    k_bsort<<<256, 256>>>(rsub);
    k_p12<<<256, 256>>>(semb, w1);
    k_rel2<<<1024, 256>>>(b1, w2, b2);
    k_init<<<512, 256>>>(x);
    for (int t = 0; t < LL; t++) {
        k_stepF<<<512, 256>>>(t);
    }
    k_out<<<dim3(16, 32), 256>>>(out);
}

// round 8
// speedup vs baseline: 1.4040x; 1.4040x over previous
#include <cuda_runtime.h>

#define BB 64
#define SZ 2048
#define LL 16
#define AA 64
#define HH 256
#define RR 65536
#define XW (SZ + LL)
#define BPB 4   // buckets per step-block -> 512 blocks

#define MW1_PITCH 196   // 192 + 4 pad; stride%8==4 -> conflict-free LDS.128 phases
#define MW1_SMEM_BYTES (256 * MW1_PITCH * 4)

// ---------------- scratch (static device globals; no allocs) ----------------
__device__ __align__(16) float    g_P1[SZ * HH];
__device__ __align__(16) float    g_P2[SZ * HH];
__device__ __align__(16) unsigned g_relT[RR * AA];        // relation rows as tf32 bits, CSR order
__device__ __align__(16) unsigned g_metaT32[LL * BB * AA]; // tf32 bits, [(t*64+b)][k]
__device__ __align__(16) float    g_stateAll[LL + 1][SZ * BB]; // [t][o][b]
__device__ int g_perm[RR];
__device__ int g_subjS[RR];
__device__ int g_objS[RR];
__device__ int g_counts[SZ];
__device__ int g_rowptr[SZ + 1];
__device__ int g_offs[SZ];

// ---------------- tf32 mma helpers ----------------
__device__ __forceinline__ unsigned f2t(float f) {
    unsigned u;
    asm("cvt.rna.tf32.f32 %0, %1;" : "=r"(u) : "f"(f));
    return u;
}
__device__ __forceinline__ void mma8(float4& d, unsigned a0, unsigned a1, unsigned a2,
                                     unsigned a3, unsigned b0, unsigned b1) {
    asm volatile(
        "mma.sync.aligned.m16n8k8.row.col.f32.tf32.tf32.f32 "
        "{%0,%1,%2,%3},{%4,%5,%6,%7},{%8,%9},{%0,%1,%2,%3};"
        : "+f"(d.x), "+f"(d.y), "+f"(d.z), "+f"(d.w)
        : "r"(a0), "r"(a1), "r"(a2), "r"(a3), "r"(b0), "r"(b1));
}

__device__ __forceinline__ float sigf(float v) {
    return __fdividef(1.f, 1.f + __expf(-v));
}

// ---------------- CSR build (deterministic) ----------------
__global__ void k_zero() {
    int i = blockIdx.x * blockDim.x + threadIdx.x;
    if (i < SZ) g_counts[i] = 0;
}

__global__ void k_hist(const int* __restrict__ robj) {
    int e = blockIdx.x * blockDim.x + threadIdx.x;
    if (e < RR) atomicAdd(&g_counts[robj[e]], 1);
}

__global__ void k_scan() {  // 1 block, 1024 threads: scan of 2048
    __shared__ int sA[SZ], sB[SZ];
    int tid = threadIdx.x;
    for (int i = tid; i < SZ; i += 1024) sA[i] = g_counts[i];
    __syncthreads();
    int* src = sA; int* dst = sB;
    for (int off = 1; off < SZ; off <<= 1) {
        for (int i = tid; i < SZ; i += 1024)
            dst[i] = src[i] + (i >= off ? src[i - off] : 0);
        __syncthreads();
        int* t = src; src = dst; dst = t;
    }
    for (int i = tid; i < SZ; i += 1024) {
        g_rowptr[i + 1] = src[i];
        g_offs[i] = (i == 0) ? 0 : src[i - 1];
    }
    if (tid == 0) g_rowptr[0] = 0;
}

__global__ void k_scatter(const int* __restrict__ robj) {
    int e = blockIdx.x * blockDim.x + threadIdx.x;
    if (e < RR) {
        int pos = atomicAdd(&g_offs[robj[e]], 1);
        g_perm[pos] = e;
    }
}

// sort each bucket's edge ids ascending (determinism), emit subj/obj in sorted order
__global__ void k_bsort(const int* __restrict__ rsub) {
    __shared__ int buf[8][208];
    int wid = threadIdx.x >> 5, lane = threadIdx.x & 31;
    int o = blockIdx.x * 8 + wid;
    int s = g_rowptr[o], e = g_rowptr[o + 1], n = e - s;
    if (n > 0 && n <= 208) {
        for (int i = lane; i < n; i += 32) buf[wid][i] = g_perm[s + i];
        __syncwarp();
        for (int r = 0; r < n; r++) {           // odd-even transposition
            int par = r & 1;
            for (int i = par + 2 * lane; i + 1 < n; i += 64) {
                int a = buf[wid][i], b = buf[wid][i + 1];
                if (a > b) { buf[wid][i] = b; buf[wid][i + 1] = a; }
            }
            __syncwarp();
        }
        for (int i = lane; i < n; i += 32) {
            int p = buf[wid][i];
            g_perm[s + i] = p;
            g_subjS[s + i] = rsub[p];
            g_objS[s + i] = o;
        }
    } else {
        for (int i = lane; i < n; i += 32) {
            int p = g_perm[s + i];
            g_subjS[s + i] = rsub[p];
            g_objS[s + i] = o;
        }
    }
}

// ---------------- P1/P2 = state_emb @ W1 halves ----------------
__global__ void k_p12(const float* __restrict__ emb, const float* __restrict__ w1) {
    __shared__ float es[8][64];
    int tid = threadIdx.x;
    int r0 = blockIdx.x * 8;
    for (int i = tid; i < 512; i += 256) es[i >> 6][i & 63] = emb[r0 * 64 + i];
    __syncthreads();
    float a1[8], a2[8];
#pragma unroll
    for (int r = 0; r < 8; r++) { a1[r] = 0.f; a2[r] = 0.f; }
    for (int k = 0; k < 64; k++) {
        float wa = w1[k * HH + tid];
        float wb = w1[(64 + k) * HH + tid];
#pragma unroll
        for (int r = 0; r < 8; r++) {
            a1[r] += es[r][k] * wa;
            a2[r] += es[r][k] * wb;
        }
    }
#pragma unroll
    for (int r = 0; r < 8; r++) {
        g_P1[(r0 + r) * HH + tid] = a1[r];
        g_P2[(r0 + r) * HH + tid] = a2[r];
    }
}

// ---------------- relation rows via tf32 mma; output tf32 bits ----------------
// block: 64 edges, N=64, K=256 in 4 chunks of 64. 256 threads = 8 warps (4m x 2n).
__global__ void k_rel2(const float* __restrict__ b1v, const float* __restrict__ w2,
                       const float* __restrict__ b2v) {
    __shared__ float hs[64][68];
    __shared__ float ws[64][68];
    __shared__ int ssub[64], sobj[64];
    int tid = threadIdx.x;
    int e0 = blockIdx.x * 64;
    if (tid < 64) { ssub[tid] = g_subjS[e0 + tid]; sobj[tid] = g_objS[e0 + tid]; }
    __syncthreads();
    int warp = tid >> 5, lane = tid & 31;
    int wm = warp & 3, wn = warp >> 2;
    int g = lane >> 2, tg = lane & 3;
    int r0 = wm * 16, n0 = wn * 32;
    float4 acc[4] = {};
    for (int kc = 0; kc < 4; kc++) {
        for (int i = tid; i < 64 * 16; i += 256) {
            int r = i >> 4, c = (i & 15) * 4;
            float4 p1 = *(const float4*)&g_P1[ssub[r] * HH + kc * 64 + c];
            float4 p2 = *(const float4*)&g_P2[sobj[r] * HH + kc * 64 + c];
            float4 bb = *(const float4*)&b1v[kc * 64 + c];
            float4 h;
            h.x = fmaxf(p1.x + p2.x + bb.x, 0.f);
            h.y = fmaxf(p1.y + p2.y + bb.y, 0.f);
            h.z = fmaxf(p1.z + p2.z + bb.z, 0.f);
            h.w = fmaxf(p1.w + p2.w + bb.w, 0.f);
            *(float4*)&hs[r][c] = h;
            *(float4*)&ws[r][c] = *(const float4*)&w2[(kc * 64 + r) * 64 + c];
        }
        __syncthreads();
#pragma unroll
        for (int ks = 0; ks < 8; ks++) {
            int kk = ks * 8;
            unsigned a0 = f2t(hs[r0 + g][kk + tg]);
            unsigned a1 = f2t(hs[r0 + g + 8][kk + tg]);
            unsigned a2 = f2t(hs[r0 + g][kk + tg + 4]);
            unsigned a3 = f2t(hs[r0 + g + 8][kk + tg + 4]);
#pragma unroll
            for (int nf = 0; nf < 4; nf++) {
                int n = n0 + nf * 8 + g;
                unsigned b0 = f2t(ws[kk + tg][n]);
                unsigned b1 = f2t(ws[kk + tg + 4][n]);
                mma8(acc[nf], a0, a1, a2, a3, b0, b1);
            }
        }
        __syncthreads();
    }
#pragma unroll
    for (int nf = 0; nf < 4; nf++) {
        int col = n0 + nf * 8 + 2 * tg;
        float bx = b2v[col], by = b2v[col + 1];
        int row = e0 + r0 + g;
        uint2 v0 = {f2t(acc[nf].x + bx), f2t(acc[nf].y + by)};
        uint2 v1 = {f2t(acc[nf].z + bx), f2t(acc[nf].w + by)};
        *(uint2*)&g_relT[row * 64 + col] = v0;
        *(uint2*)&g_relT[(row + 8) * 64 + col] = v1;
    }
}

// ---------------- meta recurrence v3: one batch per block, mw1 resident in smem ----
// 64 blocks x 256 threads. mw1 transposed into 200KB dynamic smem once, reused 16x.
// Layer1 inner loop: weight rows via conflict-free LDS.128, z via broadcast LDS.128.
__global__ void __launch_bounds__(256) k_meta3(
        const int* __restrict__ x, const float* __restrict__ aemb,
        const float* __restrict__ pemb, const float* __restrict__ qw,
        const float* __restrict__ qb, const float* __restrict__ mw1,
        const float* __restrict__ mb1, const float* __restrict__ mw2,
        const float* __restrict__ mb2, const float* __restrict__ minit) {
    extern __shared__ __align__(16) float sW[];   // [256][MW1_PITCH]
    __shared__ __align__(16) float sent[16][132];
    __shared__ __align__(16) float meta[64];
    __shared__ __align__(16) float query[128];
    __shared__ float attn[16];
    __shared__ __align__(16) float z[192];
    __shared__ __align__(16) float hid[256];
    int t = threadIdx.x;
    int b = blockIdx.x;

    // stage mw1 transposed: sW[col][k] = mw1[k][col]; global reads coalesced
    for (int k = 0; k < 192; k++) sW[t * MW1_PITCH + k] = mw1[k * HH + t];

    for (int i = t; i < 16 * 128; i += 256) {
        int l = i >> 7, d = i & 127;
        int a = x[b * XW + SZ + l];
        sent[l][d] = (d < 64) ? aemb[a * 64 + d] : pemb[l * 64 + (d - 64)];
    }
    if (t < 64) meta[t] = minit[t];
    __syncthreads();

    for (int st = 0; st < 16; st++) {
        // (a) query[j] = meta . qw[:,j] + qb[j]; 2 threads per output
        {
            int j = t >> 1, s = t & 1;
            float q = 0.f;
#pragma unroll
            for (int k = s * 32; k < s * 32 + 32; k++) q += meta[k] * qw[k * 128 + j];
            q += __shfl_xor_sync(0xffffffffu, q, 1);
            if (s == 0) query[j] = q + qb[j];
        }
        __syncthreads();
        // (b) scores: 16 outputs, 16 threads each
        {
            int l = t >> 4, s = t & 15;
            float sc = 0.f;
#pragma unroll
            for (int i = 0; i < 8; i++) {
                int d = s + 16 * i;
                sc += query[d] * sent[l][d];
            }
            sc += __shfl_xor_sync(0xffffffffu, sc, 1);
            sc += __shfl_xor_sync(0xffffffffu, sc, 2);
            sc += __shfl_xor_sync(0xffffffffu, sc, 4);
            sc += __shfl_xor_sync(0xffffffffu, sc, 8);
            if (s == 0) attn[l] = sc;
        }
        __syncthreads();
        // (c) softmax over 16
        if (t < 16) {
            float v = attn[t];
            float m = v;
#pragma unroll
            for (int o = 8; o; o >>= 1) m = fmaxf(m, __shfl_xor_sync(0xffffu, m, o));
            float e = __expf(v - m);
            float ssum = e;
#pragma unroll
            for (int o = 8; o; o >>= 1) ssum += __shfl_xor_sync(0xffffu, ssum, o);
            attn[t] = e / ssum;
        }
        __syncthreads();
        // (d) attended -> z[64+j]; copy meta -> z[0:64]
        {
            int j = t >> 1, s = t & 1;
            float at = 0.f;
#pragma unroll
            for (int l = s * 8; l < s * 8 + 8; l++) at += attn[l] * sent[l][j];
            at += __shfl_xor_sync(0xffffffffu, at, 1);
            if (s == 0) {
                z[64 + j] = at;
                if (j < 64) z[j] = meta[j];
            }
        }
        __syncthreads();
        // (e) layer1 from smem weights: thread t -> output t
        {
            const float4* wrow = (const float4*)&sW[t * MW1_PITCH];
            const float4* z4 = (const float4*)z;
            float a0 = 0.f, a1 = 0.f, a2 = 0.f, a3 = 0.f;
#pragma unroll
            for (int i = 0; i < 48; i += 4) {
                float4 w0 = wrow[i],     zv0 = z4[i];
                float4 w1v = wrow[i + 1], zv1 = z4[i + 1];
                float4 w2v = wrow[i + 2], zv2 = z4[i + 2];
                float4 w3v = wrow[i + 3], zv3 = z4[i + 3];
                a0 += w0.x * zv0.x + w0.y * zv0.y + w0.z * zv0.z + w0.w * zv0.w;
                a1 += w1v.x * zv1.x + w1v.y * zv1.y + w1v.z * zv1.z + w1v.w * zv1.w;
                a2 += w2v.x * zv2.x + w2v.y * zv2.y + w2v.z * zv2.z + w2v.w * zv2.w;
                a3 += w3v.x * zv3.x + w3v.y * zv3.y + w3v.z * zv3.z + w3v.w * zv3.w;
            }
            hid[t] = fmaxf((a0 + a1) + (a2 + a3) + mb1[t], 0.f);
        }
        __syncthreads();
        // (f) layer2: 64 outputs, 4 threads each (k interleaved), 2 accumulators
        {
            int j = t >> 2, s = t & 3;
            float a0 = 0.f, a1 = 0.f;
#pragma unroll
            for (int i = 0; i < 64; i += 2) {
                a0 += hid[4 * i + s]       * mw2[(4 * i + s) * 64 + j];
                a1 += hid[4 * (i + 1) + s] * mw2[(4 * (i + 1) + s) * 64 + j];
            }
            float m = a0 + a1;
            m += __shfl_xor_sync(0xffffffffu, m, 1);
            m += __shfl_xor_sync(0xffffffffu, m, 2);
            if (s == 0) meta[j] = m + mb2[j];
        }
        __syncthreads();
        if (t < 64) g_metaT32[(st * 64 + b) * 64 + t] = f2t(meta[t]);
    }
}

// ---------------- init transposed state ----------------
__global__ void k_init(const int* __restrict__ x) {
    int i = blockIdx.x * blockDim.x + threadIdx.x;  // 131072
    int b = i >> 11, o = i & 2047;
    g_stateAll[0][o * 64 + b] = (float)x[b * XW + o];
}

// ---------------- fused step: MMA dots + sigmoid + gather + segmented reduce ------
// block = 4 buckets (512 blocks), 256 threads = 8 warps (4m x 2n) over 64x64 tiles.
__global__ void __launch_bounds__(256) k_stepF(int t) {
    __shared__ __align__(16) unsigned tileBuf[64 * 68];  // rel tf32 bits, reused as prod floats
    __shared__ __align__(16) unsigned metaS[64 * 68];
    __shared__ float acc[(BPB + 1) * 64];
    __shared__ int ssubj[64];
    __shared__ unsigned char rowb[64];
    const float* __restrict__ stIn = g_stateAll[t];
    float* __restrict__ stOut = g_stateAll[t + 1];
    int tid = threadIdx.x;
    int bkt0 = blockIdx.x * BPB;
    int eStart = g_rowptr[bkt0];
    int eEnd = g_rowptr[bkt0 + BPB];

    const unsigned* mt = &g_metaT32[t * 64 * 64];
    for (int i = tid; i < 64 * 16; i += 256) {
        int r = i >> 4, c = (i & 15) * 4;
        *(uint4*)&metaS[r * 68 + c] = *(const uint4*)&mt[r * 64 + c];
    }
    for (int i = tid; i < (BPB + 1) * 64; i += 256) acc[i] = 0.f;
    __syncthreads();

    int warp = tid >> 5, lane = tid & 31;
    int wm = warp & 3, wn = warp >> 2;
    int g = lane >> 2, tg = lane & 3;
    int r0 = wm * 16, n0 = wn * 32;
    int q = tid >> 6, col = tid & 63;

    for (int base = eStart; base < eEnd; base += 64) {
        int m = min(64, eEnd - base);
        // fill rel tile (tf32 bits) + subj + local bucket ids
        for (int i = tid; i < 64 * 16; i += 256) {
            int r = i >> 4, c = (i & 15) * 4;
            uint4 v = (r < m) ? *(const uint4*)&g_relT[(base + r) * 64 + c]
                              : make_uint4(0u, 0u, 0u, 0u);
            *(uint4*)&tileBuf[r * 68 + c] = v;
        }
        if (tid < 64) {
            if (tid < m) {
                ssubj[tid] = g_subjS[base + tid];
                rowb[tid] = (unsigned char)(g_objS[base + tid] - bkt0);
            } else { ssubj[tid] = 0; rowb[tid] = BPB; }
        }
        __syncthreads();

        float4 accf[4] = {};
#pragma unroll
        for (int ks = 0; ks < 8; ks++) {
            int kk = ks * 8;
            unsigned a0 = tileBuf[(r0 + g) * 68 + kk + tg];
            unsigned a1 = tileBuf[(r0 + g + 8) * 68 + kk + tg];
            unsigned a2 = tileBuf[(r0 + g) * 68 + kk + tg + 4];
            unsigned a3 = tileBuf[(r0 + g + 8) * 68 + kk + tg + 4];
#pragma unroll
            for (int nf = 0; nf < 4; nf++) {
                int n = n0 + nf * 8 + g;
                unsigned b0 = metaS[n * 68 + kk + tg];
                unsigned b1 = metaS[n * 68 + kk + tg + 4];
                mma8(accf[nf], a0, a1, a2, a3, b0, b1);
            }
        }
        __syncthreads();  // everyone done reading tileBuf as rel

        // epilogue: prod[e][b] = state[subj[e]][b] * sigmoid(D[e][b]) into tileBuf
        float* prod = (float*)tileBuf;
        int rA = r0 + g, rB = rA + 8;
        int sjA = ssubj[rA], sjB = ssubj[rB];
#pragma unroll
        for (int nf = 0; nf < 4; nf++) {
            int c = n0 + nf * 8 + 2 * tg;
            float2 svA = *(const float2*)&stIn[sjA * 64 + c];
            float2 svB = *(const float2*)&stIn[sjB * 64 + c];
            float2 pA = {svA.x * sigf(accf[nf].x), svA.y * sigf(accf[nf].y)};
            float2 pB = {svB.x * sigf(accf[nf].z), svB.y * sigf(accf[nf].w)};
            *(float2*)&prod[rA * 68 + c] = pA;
            *(float2*)&prod[rB * 68 + c] = pB;
        }
        __syncthreads();

        // segmented reduction: thread (q, col) sums rows [16q,16q+16) by bucket
        {
            float s = 0.f;
            int cur = rowb[q * 16];
#pragma unroll
            for (int r = q * 16; r < q * 16 + 16; r++) {
                int lb = rowb[r];
                if (lb != cur) { atomicAdd(&acc[cur * 64 + col], s); s = 0.f; cur = lb; }
                s += prod[r * 68 + col];
            }
            atomicAdd(&acc[cur * 64 + col], s);
        }
        __syncthreads();
    }

    for (int i = tid; i < BPB * 64; i += 256) {
        int lb = i >> 6, c = i & 63;
        stOut[(bkt0 + lb) * 64 + c] = acc[lb * 64 + c];
    }
}

// ---------------- final transpose: out[b][t][o] = stateAll[t+1][o][b] -------------
__global__ void k_out(float* __restrict__ out) {
    __shared__ float tile[64][65];
    int t = blockIdx.x, o0 = blockIdx.y * 64;
    const float* st = g_stateAll[t + 1];
    for (int i = threadIdx.x; i < 64 * 64; i += 256) {
        int r = i >> 6, b = i & 63;
        tile[b][r] = st[(o0 + r) * 64 + b];
    }
    __syncthreads();
    for (int i = threadIdx.x; i < 64 * 64; i += 256) {
        int b = i >> 6, c = i & 63;
        out[(size_t)b * (LL * SZ) + t * SZ + o0 + c] = tile[b][c];
    }
}

extern "C" void kernel_launch(void* const* d_in, const int* in_sizes, int n_in,
                              void* d_out, int out_size) {
    const int*   x     = (const int*)d_in[0];
    const int*   rsub  = (const int*)d_in[1];
    const int*   robj  = (const int*)d_in[2];
    const float* aemb  = (const float*)d_in[3];
    const float* pemb  = (const float*)d_in[4];
    const float* semb  = (const float*)d_in[5];
    const float* w1    = (const float*)d_in[6];
    const float* b1    = (const float*)d_in[7];
    const float* w2    = (const float*)d_in[8];
    const float* b2    = (const float*)d_in[9];
    const float* qw    = (const float*)d_in[10];
    const float* qb    = (const float*)d_in[11];
    const float* mw1   = (const float*)d_in[12];
    const float* mb1   = (const float*)d_in[13];
    const float* mw2   = (const float*)d_in[14];
    const float* mb2   = (const float*)d_in[15];
    const float* minit = (const float*)d_in[16];
    float* out = (float*)d_out;

    cudaFuncSetAttribute(k_meta3, cudaFuncAttributeMaxDynamicSharedMemorySize,
                         MW1_SMEM_BYTES);

    // k_meta3 at the 4th launch slot (ncu profiles that slot).
    k_zero<<<8, 256>>>();
    k_hist<<<256, 256>>>(robj);
    k_scan<<<1, 1024>>>();
    k_meta3<<<64, 256, MW1_SMEM_BYTES>>>(x, aemb, pemb, qw, qb, mw1, mb1, mw2, mb2, minit);
    k_scatter<<<256, 256>>>(robj);
    k_bsort<<<256, 256>>>(rsub);
    k_p12<<<256, 256>>>(semb, w1);
    k_rel2<<<1024, 256>>>(b1, w2, b2);
    k_init<<<512, 256>>>(x);
    for (int t = 0; t < LL; t++) {
        k_stepF<<<512, 256>>>(t);
    }
    k_out<<<dim3(16, 32), 256>>>(out);
}